// round 15
// baseline (speedup 1.0000x reference)
#include <cuda_runtime.h>
#include <cuda_bf16.h>
#include <cstdint>

// ---------------- fixed problem shapes ---------------------------------------
#define TT    12
#define CIN   32
#define HID   64
#define COUT  32
#define N1C   20000
#define N2C   10000
#define E1C   320000
#define E2C   160000
#define TC    (TT*CIN)        // 384
#define ROWS1 (N1C*TT)        // 240000 (= 1875 * 128)
#define ROWS2 (N2C*TT)        // 120000
#define CAP   96

// ---------------- device scratch (static, no runtime allocation) -------------
__device__ float g_agg1[(size_t)ROWS1 * CIN];
__device__ float g_z1  [(size_t)ROWS1 * COUT];
__device__ float g_s2  [(size_t)ROWS2 * COUT];
__device__ int   g_cnt1[N1C];
__device__ int   g_cnt2[N2C];
__device__ int2  g_buk1[(size_t)N1C * CAP];
__device__ int2  g_buk2[(size_t)N2C * CAP];

__device__ __forceinline__ float lrelu(float x) { return x > 0.f ? x : 0.01f * x; }

__device__ __forceinline__ void fma4(float4& a, float w, float4 v) {
    a.x += w * v.x; a.y += w * v.y; a.z += w * v.z; a.w += w * v.w;
}
__device__ __forceinline__ float4 add4(float4 a, float4 b) {
    return make_float4(a.x + b.x, a.y + b.y, a.z + b.z, a.w + b.w);
}

// split a float pair into hi/lo bf16x2 words (x -> low 16 bits)
__device__ __forceinline__ void cvthl(float x, float y, uint32_t& h, uint32_t& l) {
    __nv_bfloat16 hx = __float2bfloat16(x), hy = __float2bfloat16(y);
    __nv_bfloat16 lx = __float2bfloat16(x - __bfloat162float(hx));
    __nv_bfloat16 ly = __float2bfloat16(y - __bfloat162float(hy));
    __nv_bfloat162 hp(hx, hy), lp(lx, ly);
    h = *reinterpret_cast<uint32_t*>(&hp);
    l = *reinterpret_cast<uint32_t*>(&lp);
}

// HMMA m16n8k16 row.col bf16 -> f32
__device__ __forceinline__ void mma16816(float* d, const uint32_t* a, uint32_t b0, uint32_t b1) {
    asm volatile(
        "mma.sync.aligned.m16n8k16.row.col.f32.bf16.bf16.f32 "
        "{%0,%1,%2,%3}, {%4,%5,%6,%7}, {%8,%9}, {%0,%1,%2,%3};"
        : "+f"(d[0]), "+f"(d[1]), "+f"(d[2]), "+f"(d[3])
        : "r"(a[0]), "r"(a[1]), "r"(a[2]), "r"(a[3]), "r"(b0), "r"(b1));
}

// ---------------- bucket build -------------------------------------------------
__global__ void k_zero() {
    int i = blockIdx.x * blockDim.x + threadIdx.x;
    if (i < N1C) g_cnt1[i] = 0;
    if (i < N2C) g_cnt2[i] = 0;
}

__global__ void k_build(const int* __restrict__ src1, const int* __restrict__ dst1,
                        const float* __restrict__ ew1,
                        const int* __restrict__ src2, const int* __restrict__ dst2,
                        const float* __restrict__ ew2) {
    int i = blockIdx.x * blockDim.x + threadIdx.x;
    if (i < E1C) {
        int d = dst1[i];
        int p = atomicAdd(&g_cnt1[d], 1);
        if (p < CAP) g_buk1[(size_t)d * CAP + p] = make_int2(src1[i], __float_as_int(ew1[i]));
    } else if (i < E1C + E2C) {
        int e = i - E1C;
        int d = dst2[e];
        int p = atomicAdd(&g_cnt2[d], 1);
        if (p < CAP) g_buk2[(size_t)d * CAP + p] = make_int2(src2[e], __float_as_int(ew2[e]));
    }
}

// ---------------- layer-1 aggregation: 3 warps per dst (j-thirds) --------------
// Warp (d, j) owns quads q = j*32 + lane of the 384-wide (t,c) row.
// Per edge: 1 warp-LDG.128; 8-edge unroll -> 8 gathers in flight; low regs.
__global__ void __launch_bounds__(256) k_agg1(const float* __restrict__ nf, int nsrc) {
    int d = blockIdx.x * 8 + (threadIdx.x >> 5);
    if (d >= N1C) return;
    int lane = threadIdx.x & 31;
    int q = blockIdx.y * 32 + lane;                 // quad index 0..95
    int n = min(g_cnt1[d], CAP);
    const int2* eb = &g_buk1[(size_t)d * CAP];
    size_t off = (size_t)(q >> 3) * ((size_t)nsrc * CIN) + (q & 7) * 4;
    float4 A0 = {}, A1 = {}, A2 = {}, A3 = {}, A4 = {}, A5 = {}, A6 = {}, A7 = {};
    int i = 0;
    for (; i + 8 <= n; i += 8) {
        int2 e0 = __ldg(&eb[i]),     e1 = __ldg(&eb[i + 1]);
        int2 e2 = __ldg(&eb[i + 2]), e3 = __ldg(&eb[i + 3]);
        int2 e4 = __ldg(&eb[i + 4]), e5 = __ldg(&eb[i + 5]);
        int2 e6 = __ldg(&eb[i + 6]), e7 = __ldg(&eb[i + 7]);
        fma4(A0, __int_as_float(e0.y), __ldg((const float4*)(nf + (size_t)e0.x * CIN + off)));
        fma4(A1, __int_as_float(e1.y), __ldg((const float4*)(nf + (size_t)e1.x * CIN + off)));
        fma4(A2, __int_as_float(e2.y), __ldg((const float4*)(nf + (size_t)e2.x * CIN + off)));
        fma4(A3, __int_as_float(e3.y), __ldg((const float4*)(nf + (size_t)e3.x * CIN + off)));
        fma4(A4, __int_as_float(e4.y), __ldg((const float4*)(nf + (size_t)e4.x * CIN + off)));
        fma4(A5, __int_as_float(e5.y), __ldg((const float4*)(nf + (size_t)e5.x * CIN + off)));
        fma4(A6, __int_as_float(e6.y), __ldg((const float4*)(nf + (size_t)e6.x * CIN + off)));
        fma4(A7, __int_as_float(e7.y), __ldg((const float4*)(nf + (size_t)e7.x * CIN + off)));
    }
    for (; i < n; i++) {
        int2 e = __ldg(&eb[i]);
        fma4(A0, __int_as_float(e.y), __ldg((const float4*)(nf + (size_t)e.x * CIN + off)));
    }
    float4 R = add4(add4(add4(A0, A1), add4(A2, A3)), add4(add4(A4, A5), add4(A6, A7)));
    *(float4*)&g_agg1[(size_t)d * TC + q * 4] = R;
}

// ---------------- layer-2 aggregation + fused epilogue: 3 warps per dst --------
__global__ void __launch_bounds__(256) k_agg2f(const float* __restrict__ b2,
                                               float* __restrict__ out) {
    int d = blockIdx.x * 8 + (threadIdx.x >> 5);
    if (d >= N2C) return;
    int lane = threadIdx.x & 31;
    int q = blockIdx.y * 32 + lane;                 // quad index 0..95
    int n = min(g_cnt2[d], CAP);
    const int2* eb = &g_buk2[(size_t)d * CAP];
    unsigned off = q * 4;
    float4 A0 = {}, A1 = {}, A2 = {}, A3 = {}, A4 = {}, A5 = {}, A6 = {}, A7 = {};
    int i = 0;
    for (; i + 8 <= n; i += 8) {
        int2 e0 = __ldg(&eb[i]),     e1 = __ldg(&eb[i + 1]);
        int2 e2 = __ldg(&eb[i + 2]), e3 = __ldg(&eb[i + 3]);
        int2 e4 = __ldg(&eb[i + 4]), e5 = __ldg(&eb[i + 5]);
        int2 e6 = __ldg(&eb[i + 6]), e7 = __ldg(&eb[i + 7]);
        fma4(A0, __int_as_float(e0.y), __ldg((const float4*)(g_z1 + (size_t)e0.x * TC + off)));
        fma4(A1, __int_as_float(e1.y), __ldg((const float4*)(g_z1 + (size_t)e1.x * TC + off)));
        fma4(A2, __int_as_float(e2.y), __ldg((const float4*)(g_z1 + (size_t)e2.x * TC + off)));
        fma4(A3, __int_as_float(e3.y), __ldg((const float4*)(g_z1 + (size_t)e3.x * TC + off)));
        fma4(A4, __int_as_float(e4.y), __ldg((const float4*)(g_z1 + (size_t)e4.x * TC + off)));
        fma4(A5, __int_as_float(e5.y), __ldg((const float4*)(g_z1 + (size_t)e5.x * TC + off)));
        fma4(A6, __int_as_float(e6.y), __ldg((const float4*)(g_z1 + (size_t)e6.x * TC + off)));
        fma4(A7, __int_as_float(e7.y), __ldg((const float4*)(g_z1 + (size_t)e7.x * TC + off)));
    }
    for (; i < n; i++) {
        int2 e = __ldg(&eb[i]);
        fma4(A0, __int_as_float(e.y), __ldg((const float4*)(g_z1 + (size_t)e.x * TC + off)));
    }
    float4 R = add4(add4(add4(A0, A1), add4(A2, A3)), add4(add4(A4, A5), add4(A6, A7)));
    float4 bq = __ldg((const float4*)&b2[(q & 7) * 4]);
    float4 s = *(const float4*)&g_s2[(size_t)d * TC + q * 4];
    float4 v;
    v.x = lrelu(R.x + s.x + bq.x);
    v.y = lrelu(R.y + s.y + bq.y);
    v.z = lrelu(R.z + s.z + bq.z);
    v.w = lrelu(R.w + s.w + bq.w);
    int t = q >> 3, cq = q & 7;
    *(float4*)&out[((size_t)t * N2C + d) * COUT + cq * 4] = v;
}

// ---------------- fused GEMM via mma.sync (bf16 2-split, 3 terms) --------------
__global__ void __launch_bounds__(256) k_gemm_mma(
        const float* __restrict__ nf,
        const float* __restrict__ W1s, const float* __restrict__ W1n,
        const float* __restrict__ b1,
        const float* __restrict__ W2s, const float* __restrict__ W2n,
        int nsrc) {
    __shared__ uint4 sW1[1024];   // 16 KB: stage-1 weights, fragment-packed
    __shared__ uint4 sW2[1024];   // 16 KB: stage-2 weights
    int tid = threadIdx.x;

    // prologue: pack W1' = [W1s|W1n] (n=h, k=cat) and W2' = [W2n;W2s] (k=h)
    for (int i = tid; i < 2048; i += 256) {
        int e = i & 1023;
        int ln = e & 31, s = (e >> 5) & 3, j = e >> 7;
        int n = j * 8 + (ln >> 2);
        int k = s * 16 + (ln & 3) * 2;
        const float* base;
        if (i < 1024) base = (s < 2) ? &W1s[n * 32 + k] : &W1n[n * 32 + (k - 32)];
        else          base = (n < 32) ? &W2n[n * 64 + k] : &W2s[(n - 32) * 64 + k];
        uint32_t b0h, b0l, b1h, b1l;
        cvthl(__ldg(base),     __ldg(base + 1), b0h, b0l);
        cvthl(__ldg(base + 8), __ldg(base + 9), b1h, b1l);
        (i < 1024 ? sW1 : sW2)[e] = make_uint4(b0h, b0l, b1h, b1l);
    }
    __syncthreads();

    int lane = tid & 31, wid = tid >> 5;
    int mb = blockIdx.x * 128 + wid * 16;
    int m0 = mb + (lane >> 2), m1 = m0 + 8;
    int ko = (lane & 3) * 2;

    // stage-1 A fragments straight from gmem (hi/lo split)
    uint32_t Ah[4][4], Al[4][4];
    {
        int nd0 = m0 / TT, t0 = m0 - nd0 * TT;
        int nd1 = m1 / TT, t1 = m1 - nd1 * TT;
        const float* p0 = &nf[((size_t)t0 * nsrc + nd0) * CIN];
        const float* p1 = &nf[((size_t)t1 * nsrc + nd1) * CIN];
        const float* q0 = &g_agg1[(size_t)m0 * CIN];
        const float* q1 = &g_agg1[(size_t)m1 * CIN];
        #pragma unroll
        for (int s = 0; s < 4; s++) {
            int k = s * 16 + ko;
            const float* r0p = (s < 2) ? p0 + k : q0 + (k - 32);
            const float* r1p = (s < 2) ? p1 + k : q1 + (k - 32);
            float2 v0 = *(const float2*)r0p;
            float2 v1 = *(const float2*)r1p;
            float2 v2 = *(const float2*)(r0p + 8);
            float2 v3 = *(const float2*)(r1p + 8);
            cvthl(v0.x, v0.y, Ah[s][0], Al[s][0]);
            cvthl(v1.x, v1.y, Ah[s][1], Al[s][1]);
            cvthl(v2.x, v2.y, Ah[s][2], Al[s][2]);
            cvthl(v3.x, v3.y, Ah[s][3], Al[s][3]);
        }
    }

    // stage 1: D = A @ W1'^T (3 split terms), K=64
    float D[8][4];
    #pragma unroll
    for (int j = 0; j < 8; j++) D[j][0] = D[j][1] = D[j][2] = D[j][3] = 0.f;
    #pragma unroll
    for (int j = 0; j < 8; j++)
        #pragma unroll
        for (int s = 0; s < 4; s++) {
            uint4 w = sW1[(j * 4 + s) * 32 + lane];
            mma16816(D[j], Ah[s], w.x, w.z);
            mma16816(D[j], Al[s], w.x, w.z);
            mma16816(D[j], Ah[s], w.y, w.w);
        }

    // bias + leaky relu (h1, in registers)
    #pragma unroll
    for (int j = 0; j < 8; j++) {
        int n0 = j * 8 + ko;
        float be = __ldg(&b1[n0]), bo = __ldg(&b1[n0 + 1]);
        D[j][0] = lrelu(D[j][0] + be); D[j][1] = lrelu(D[j][1] + bo);
        D[j][2] = lrelu(D[j][2] + be); D[j][3] = lrelu(D[j][3] + bo);
    }

    // stage-2 A fragments: direct register relayout of D
    uint32_t Bh[4][4], Bl[4][4];
    #pragma unroll
    for (int s = 0; s < 4; s++) {
        cvthl(D[2*s][0],   D[2*s][1],   Bh[s][0], Bl[s][0]);
        cvthl(D[2*s][2],   D[2*s][3],   Bh[s][1], Bl[s][1]);
        cvthl(D[2*s+1][0], D[2*s+1][1], Bh[s][2], Bl[s][2]);
        cvthl(D[2*s+1][2], D[2*s+1][3], Bh[s][3], Bl[s][3]);
    }

    // stage 2: [z1 | s2] = h1 @ W2'^T; skip s-half when warp rows >= ROWS2
    int jmax = (mb < ROWS2) ? 8 : 4;
    for (int j2 = 0; j2 < jmax; j2++) {
        float E[4] = {0.f, 0.f, 0.f, 0.f};
        #pragma unroll
        for (int s = 0; s < 4; s++) {
            uint4 w = sW2[(j2 * 4 + s) * 32 + lane];
            mma16816(E, Bh[s], w.x, w.z);
            mma16816(E, Bl[s], w.x, w.z);
            mma16816(E, Bh[s], w.y, w.w);
        }
        if (j2 < 4) {
            int col = j2 * 8 + ko;
            *(float2*)&g_z1[(size_t)m0 * COUT + col] = make_float2(E[0], E[1]);
            *(float2*)&g_z1[(size_t)m1 * COUT + col] = make_float2(E[2], E[3]);
        } else {
            int col = (j2 - 4) * 8 + ko;
            if (m0 < ROWS2) *(float2*)&g_s2[(size_t)m0 * COUT + col] = make_float2(E[0], E[1]);
            if (m1 < ROWS2) *(float2*)&g_s2[(size_t)m1 * COUT + col] = make_float2(E[2], E[3]);
        }
    }
}

// ---------------- launch --------------------------------------------------------
extern "C" void kernel_launch(void* const* d_in, const int* in_sizes, int n_in,
                              void* d_out, int out_size) {
    const float* nf   = (const float*)d_in[0];
    const int*   src1 = (const int*)  d_in[1];
    const int*   dst1 = (const int*)  d_in[2];
    const float* ew1  = (const float*)d_in[3];
    const int*   src2 = (const int*)  d_in[4];
    const int*   dst2 = (const int*)  d_in[5];
    const float* ew2  = (const float*)d_in[6];
    const float* W1s  = (const float*)d_in[7];
    const float* W1n  = (const float*)d_in[8];
    const float* b1   = (const float*)d_in[9];
    const float* W2s  = (const float*)d_in[10];
    const float* W2n  = (const float*)d_in[11];
    const float* b2   = (const float*)d_in[12];
    float* out = (float*)d_out;

    int nsrc = in_sizes[0] / (TT * CIN);   // 50000

    k_zero    <<<(N1C + 255) / 256, 256>>>();
    k_build   <<<(E1C + E2C + 255) / 256, 256>>>(src1, dst1, ew1, src2, dst2, ew2);
    k_agg1    <<<dim3((N1C + 7) / 8, 3), 256>>>(nf, nsrc);
    k_gemm_mma<<<ROWS1 / 128, 256>>>(nf, W1s, W1n, b1, W2s, W2n, nsrc);
    k_agg2f   <<<dim3((N2C + 7) / 8, 3), 256>>>(b2, out);
}

// round 16
// speedup vs baseline: 1.0242x; 1.0242x over previous
#include <cuda_runtime.h>
#include <cuda_bf16.h>
#include <cstdint>

// ---------------- fixed problem shapes ---------------------------------------
#define TT    12
#define CIN   32
#define HID   64
#define COUT  32
#define N1C   20000
#define N2C   10000
#define E1C   320000
#define E2C   160000
#define TC    (TT*CIN)        // 384
#define ROWS1 (N1C*TT)        // 240000 (= 1875 * 128)
#define ROWS2 (N2C*TT)        // 120000 (32-aligned)
#define CAP   96

// ---------------- device scratch (static, no runtime allocation) -------------
__device__ float g_agg1[(size_t)ROWS1 * CIN];
__device__ float g_z1  [(size_t)ROWS1 * COUT];
__device__ float g_s2  [(size_t)ROWS2 * COUT];
__device__ int   g_cnt1[N1C];
__device__ int   g_cnt2[N2C];
__device__ int2  g_buk1[(size_t)N1C * CAP];
__device__ int2  g_buk2[(size_t)N2C * CAP];

__device__ __forceinline__ float lrelu(float x) { return x > 0.f ? x : 0.01f * x; }

__device__ __forceinline__ void fma4(float4& a, float w, float4 v) {
    a.x += w * v.x; a.y += w * v.y; a.z += w * v.z; a.w += w * v.w;
}
__device__ __forceinline__ float4 add4(float4 a, float4 b) {
    return make_float4(a.x + b.x, a.y + b.y, a.z + b.z, a.w + b.w);
}

// split a float pair into hi/lo bf16x2 words (x -> low 16 bits)
__device__ __forceinline__ void cvthl(float x, float y, uint32_t& h, uint32_t& l) {
    __nv_bfloat16 hx = __float2bfloat16(x), hy = __float2bfloat16(y);
    __nv_bfloat16 lx = __float2bfloat16(x - __bfloat162float(hx));
    __nv_bfloat16 ly = __float2bfloat16(y - __bfloat162float(hy));
    __nv_bfloat162 hp(hx, hy), lp(lx, ly);
    h = *reinterpret_cast<uint32_t*>(&hp);
    l = *reinterpret_cast<uint32_t*>(&lp);
}

// HMMA m16n8k16 row.col bf16 -> f32
__device__ __forceinline__ void mma16816(float* d, const uint32_t* a, uint32_t b0, uint32_t b1) {
    asm volatile(
        "mma.sync.aligned.m16n8k16.row.col.f32.bf16.bf16.f32 "
        "{%0,%1,%2,%3}, {%4,%5,%6,%7}, {%8,%9}, {%0,%1,%2,%3};"
        : "+f"(d[0]), "+f"(d[1]), "+f"(d[2]), "+f"(d[3])
        : "r"(a[0]), "r"(a[1]), "r"(a[2]), "r"(a[3]), "r"(b0), "r"(b1));
}

// ---------------- bucket build (R12 verbatim) ----------------------------------
__global__ void k_zero() {
    int i = blockIdx.x * blockDim.x + threadIdx.x;
    if (i < N1C) g_cnt1[i] = 0;
    if (i < N2C) g_cnt2[i] = 0;
}

__global__ void k_build(const int* __restrict__ src1, const int* __restrict__ dst1,
                        const float* __restrict__ ew1,
                        const int* __restrict__ src2, const int* __restrict__ dst2,
                        const float* __restrict__ ew2) {
    int i = blockIdx.x * blockDim.x + threadIdx.x;
    if (i < E1C) {
        int d = dst1[i];
        int p = atomicAdd(&g_cnt1[d], 1);
        if (p < CAP) g_buk1[(size_t)d * CAP + p] = make_int2(src1[i], __float_as_int(ew1[i]));
    } else if (i < E1C + E2C) {
        int e = i - E1C;
        int d = dst2[e];
        int p = atomicAdd(&g_cnt2[d], 1);
        if (p < CAP) g_buk2[(size_t)d * CAP + p] = make_int2(src2[e], __float_as_int(ew2[e]));
    }
}

// ---------------- layer-1 aggregation (R12 verbatim: warp per dst) -------------
__global__ void __launch_bounds__(256) k_agg1(const float* __restrict__ nf, int nsrc) {
    int d = blockIdx.x * 8 + (threadIdx.x >> 5);
    if (d >= N1C) return;
    int lane = threadIdx.x & 31;
    int n = min(g_cnt1[d], CAP);
    const int2* eb = &g_buk1[(size_t)d * CAP];
    size_t plane = (size_t)nsrc * CIN;
    size_t o0 = (size_t)(lane >> 3) * plane + (lane & 7) * 4;
    size_t o1 = o0 + 4 * plane;
    size_t o2 = o1 + 4 * plane;
    float4 A0[3] = {}, A1[3] = {}, A2[3] = {}, A3[3] = {};
    int i = 0;
    for (; i + 4 <= n; i += 4) {
        int2 e0 = __ldg(&eb[i]),     e1 = __ldg(&eb[i + 1]);
        int2 e2 = __ldg(&eb[i + 2]), e3 = __ldg(&eb[i + 3]);
        const float* p0 = nf + (size_t)e0.x * CIN;
        const float* p1 = nf + (size_t)e1.x * CIN;
        const float* p2 = nf + (size_t)e2.x * CIN;
        const float* p3 = nf + (size_t)e3.x * CIN;
        float w0 = __int_as_float(e0.y), w1 = __int_as_float(e1.y);
        float w2 = __int_as_float(e2.y), w3 = __int_as_float(e3.y);
        fma4(A0[0], w0, __ldg((const float4*)(p0 + o0)));
        fma4(A1[0], w1, __ldg((const float4*)(p1 + o0)));
        fma4(A2[0], w2, __ldg((const float4*)(p2 + o0)));
        fma4(A3[0], w3, __ldg((const float4*)(p3 + o0)));
        fma4(A0[1], w0, __ldg((const float4*)(p0 + o1)));
        fma4(A1[1], w1, __ldg((const float4*)(p1 + o1)));
        fma4(A2[1], w2, __ldg((const float4*)(p2 + o1)));
        fma4(A3[1], w3, __ldg((const float4*)(p3 + o1)));
        fma4(A0[2], w0, __ldg((const float4*)(p0 + o2)));
        fma4(A1[2], w1, __ldg((const float4*)(p1 + o2)));
        fma4(A2[2], w2, __ldg((const float4*)(p2 + o2)));
        fma4(A3[2], w3, __ldg((const float4*)(p3 + o2)));
    }
    for (; i < n; i++) {
        int2 e = __ldg(&eb[i]);
        const float* p = nf + (size_t)e.x * CIN;
        float w = __int_as_float(e.y);
        fma4(A0[0], w, __ldg((const float4*)(p + o0)));
        fma4(A0[1], w, __ldg((const float4*)(p + o1)));
        fma4(A0[2], w, __ldg((const float4*)(p + o2)));
    }
    float* op = &g_agg1[(size_t)d * TC];
    *(float4*)(op + lane * 4)       = add4(add4(A0[0], A1[0]), add4(A2[0], A3[0]));
    *(float4*)(op + lane * 4 + 128) = add4(add4(A0[1], A1[1]), add4(A2[1], A3[1]));
    *(float4*)(op + lane * 4 + 256) = add4(add4(A0[2], A1[2]), add4(A2[2], A3[2]));
}

// ---------------- layer-2 aggregation + fused epilogue (R12 verbatim) ----------
__global__ void __launch_bounds__(256) k_agg2f(const float* __restrict__ b2,
                                               float* __restrict__ out) {
    int d = blockIdx.x * 8 + (threadIdx.x >> 5);
    if (d >= N2C) return;
    int lane = threadIdx.x & 31;
    int n = min(g_cnt2[d], CAP);
    const int2* eb = &g_buk2[(size_t)d * CAP];
    int u0 = lane * 4, u1 = u0 + 128, u2 = u1 + 128;
    float4 A0[3] = {}, A1[3] = {}, A2[3] = {}, A3[3] = {};
    int i = 0;
    for (; i + 4 <= n; i += 4) {
        int2 e0 = __ldg(&eb[i]),     e1 = __ldg(&eb[i + 1]);
        int2 e2 = __ldg(&eb[i + 2]), e3 = __ldg(&eb[i + 3]);
        const float* p0 = g_z1 + (size_t)e0.x * TC;
        const float* p1 = g_z1 + (size_t)e1.x * TC;
        const float* p2 = g_z1 + (size_t)e2.x * TC;
        const float* p3 = g_z1 + (size_t)e3.x * TC;
        float w0 = __int_as_float(e0.y), w1 = __int_as_float(e1.y);
        float w2 = __int_as_float(e2.y), w3 = __int_as_float(e3.y);
        fma4(A0[0], w0, __ldg((const float4*)(p0 + u0)));
        fma4(A1[0], w1, __ldg((const float4*)(p1 + u0)));
        fma4(A2[0], w2, __ldg((const float4*)(p2 + u0)));
        fma4(A3[0], w3, __ldg((const float4*)(p3 + u0)));
        fma4(A0[1], w0, __ldg((const float4*)(p0 + u1)));
        fma4(A1[1], w1, __ldg((const float4*)(p1 + u1)));
        fma4(A2[1], w2, __ldg((const float4*)(p2 + u1)));
        fma4(A3[1], w3, __ldg((const float4*)(p3 + u1)));
        fma4(A0[2], w0, __ldg((const float4*)(p0 + u2)));
        fma4(A1[2], w1, __ldg((const float4*)(p1 + u2)));
        fma4(A2[2], w2, __ldg((const float4*)(p2 + u2)));
        fma4(A3[2], w3, __ldg((const float4*)(p3 + u2)));
    }
    for (; i < n; i++) {
        int2 e = __ldg(&eb[i]);
        const float* p = g_z1 + (size_t)e.x * TC;
        float w = __int_as_float(e.y);
        fma4(A0[0], w, __ldg((const float4*)(p + u0)));
        fma4(A0[1], w, __ldg((const float4*)(p + u1)));
        fma4(A0[2], w, __ldg((const float4*)(p + u2)));
    }
    float4 R[3];
    R[0] = add4(add4(A0[0], A1[0]), add4(A2[0], A3[0]));
    R[1] = add4(add4(A0[1], A1[1]), add4(A2[1], A3[1]));
    R[2] = add4(add4(A0[2], A1[2]), add4(A2[2], A3[2]));
    float4 bq = __ldg((const float4*)&b2[(lane & 7) * 4]);
    const float* sp = &g_s2[(size_t)d * TC];
    #pragma unroll
    for (int j = 0; j < 3; j++) {
        int q = lane + j * 32;
        float4 s = *(const float4*)(sp + q * 4);
        float4 v;
        v.x = lrelu(R[j].x + s.x + bq.x);
        v.y = lrelu(R[j].y + s.y + bq.y);
        v.z = lrelu(R[j].z + s.z + bq.z);
        v.w = lrelu(R[j].w + s.w + bq.w);
        int t = q >> 3, cq = q & 7;
        *(float4*)&out[((size_t)t * N2C + d) * COUT + cq * 4] = v;
    }
}

// ---------------- fused GEMM: 2 m16-tiles per warp (halved LDS per MMA) --------
// 128 threads = 4 warps; warp covers 32 rows (two m16 tiles). Each weight
// fragment LDS.128 now feeds 6 MMAs (3 split terms x 2 tiles) instead of 3.
// ROWS2 is 32-aligned -> the s-half/z-only branch is warp-uniform.
__global__ void __launch_bounds__(128, 3) k_gemm_mma(
        const float* __restrict__ nf,
        const float* __restrict__ W1s, const float* __restrict__ W1n,
        const float* __restrict__ b1,
        const float* __restrict__ W2s, const float* __restrict__ W2n,
        int nsrc) {
    __shared__ uint4 sW1[1024];   // 16 KB: stage-1 weights, fragment-packed
    __shared__ uint4 sW2[1024];   // 16 KB: stage-2 weights
    int tid = threadIdx.x;

    // prologue: pack W1' = [W1s|W1n] (n=h, k=cat) and W2' = [W2n;W2s] (k=h)
    for (int i = tid; i < 2048; i += 128) {
        int e = i & 1023;
        int ln = e & 31, s = (e >> 5) & 3, j = e >> 7;
        int n = j * 8 + (ln >> 2);
        int k = s * 16 + (ln & 3) * 2;
        const float* base;
        if (i < 1024) base = (s < 2) ? &W1s[n * 32 + k] : &W1n[n * 32 + (k - 32)];
        else          base = (n < 32) ? &W2n[n * 64 + k] : &W2s[(n - 32) * 64 + k];
        uint32_t b0h, b0l, b1h, b1l;
        cvthl(__ldg(base),     __ldg(base + 1), b0h, b0l);
        cvthl(__ldg(base + 8), __ldg(base + 9), b1h, b1l);
        (i < 1024 ? sW1 : sW2)[e] = make_uint4(b0h, b0l, b1h, b1l);
    }
    __syncthreads();

    int lane = tid & 31, wid = tid >> 5;
    int mb = blockIdx.x * 128 + wid * 32;       // warp: rows mb..mb+31
    int ko = (lane & 3) * 2;

    // stage-1 A fragments for both tiles (hi/lo split)
    uint32_t Ah[2][4][4], Al[2][4][4];
    #pragma unroll
    for (int tile = 0; tile < 2; tile++) {
        int m0 = mb + tile * 16 + (lane >> 2), m1 = m0 + 8;
        int nd0 = m0 / TT, t0 = m0 - nd0 * TT;
        int nd1 = m1 / TT, t1 = m1 - nd1 * TT;
        const float* p0 = &nf[((size_t)t0 * nsrc + nd0) * CIN];
        const float* p1 = &nf[((size_t)t1 * nsrc + nd1) * CIN];
        const float* q0 = &g_agg1[(size_t)m0 * CIN];
        const float* q1 = &g_agg1[(size_t)m1 * CIN];
        #pragma unroll
        for (int s = 0; s < 4; s++) {
            int k = s * 16 + ko;
            const float* r0p = (s < 2) ? p0 + k : q0 + (k - 32);
            const float* r1p = (s < 2) ? p1 + k : q1 + (k - 32);
            float2 v0 = *(const float2*)r0p;
            float2 v1 = *(const float2*)r1p;
            float2 v2 = *(const float2*)(r0p + 8);
            float2 v3 = *(const float2*)(r1p + 8);
            cvthl(v0.x, v0.y, Ah[tile][s][0], Al[tile][s][0]);
            cvthl(v1.x, v1.y, Ah[tile][s][1], Al[tile][s][1]);
            cvthl(v2.x, v2.y, Ah[tile][s][2], Al[tile][s][2]);
            cvthl(v3.x, v3.y, Ah[tile][s][3], Al[tile][s][3]);
        }
    }

    // stage 1: D = A @ W1'^T, one weight fragment feeds both tiles
    float D[2][8][4];
    #pragma unroll
    for (int tile = 0; tile < 2; tile++)
        #pragma unroll
        for (int j = 0; j < 8; j++)
            D[tile][j][0] = D[tile][j][1] = D[tile][j][2] = D[tile][j][3] = 0.f;
    #pragma unroll
    for (int j = 0; j < 8; j++)
        #pragma unroll
        for (int s = 0; s < 4; s++) {
            uint4 w = sW1[(j * 4 + s) * 32 + lane];
            #pragma unroll
            for (int tile = 0; tile < 2; tile++) {
                mma16816(D[tile][j], Ah[tile][s], w.x, w.z);
                mma16816(D[tile][j], Al[tile][s], w.x, w.z);
                mma16816(D[tile][j], Ah[tile][s], w.y, w.w);
            }
        }

    // bias + leaky relu, then convert D -> stage-2 A fragments (in registers)
    uint32_t Bh[2][4][4], Bl[2][4][4];
    #pragma unroll
    for (int tile = 0; tile < 2; tile++) {
        #pragma unroll
        for (int j = 0; j < 8; j++) {
            int n0 = j * 8 + ko;
            float be = __ldg(&b1[n0]), bo = __ldg(&b1[n0 + 1]);
            D[tile][j][0] = lrelu(D[tile][j][0] + be);
            D[tile][j][1] = lrelu(D[tile][j][1] + bo);
            D[tile][j][2] = lrelu(D[tile][j][2] + be);
            D[tile][j][3] = lrelu(D[tile][j][3] + bo);
        }
        #pragma unroll
        for (int s = 0; s < 4; s++) {
            cvthl(D[tile][2*s][0],   D[tile][2*s][1],   Bh[tile][s][0], Bl[tile][s][0]);
            cvthl(D[tile][2*s][2],   D[tile][2*s][3],   Bh[tile][s][1], Bl[tile][s][1]);
            cvthl(D[tile][2*s+1][0], D[tile][2*s+1][1], Bh[tile][s][2], Bl[tile][s][2]);
            cvthl(D[tile][2*s+1][2], D[tile][2*s+1][3], Bh[tile][s][3], Bl[tile][s][3]);
        }
    }

    // stage 2: [z1 | s2] = h1 @ W2'^T; warp-uniform skip of s-half past ROWS2
    int jmax = (mb < ROWS2) ? 8 : 4;
    for (int j2 = 0; j2 < jmax; j2++) {
        float E[2][4] = {};
        #pragma unroll
        for (int s = 0; s < 4; s++) {
            uint4 w = sW2[(j2 * 4 + s) * 32 + lane];
            #pragma unroll
            for (int tile = 0; tile < 2; tile++) {
                mma16816(E[tile], Bh[tile][s], w.x, w.z);
                mma16816(E[tile], Bl[tile][s], w.x, w.z);
                mma16816(E[tile], Bh[tile][s], w.y, w.w);
            }
        }
        #pragma unroll
        for (int tile = 0; tile < 2; tile++) {
            int m0 = mb + tile * 16 + (lane >> 2), m1 = m0 + 8;
            if (j2 < 4) {
                int col = j2 * 8 + ko;
                *(float2*)&g_z1[(size_t)m0 * COUT + col] = make_float2(E[tile][0], E[tile][1]);
                *(float2*)&g_z1[(size_t)m1 * COUT + col] = make_float2(E[tile][2], E[tile][3]);
            } else {
                int col = (j2 - 4) * 8 + ko;
                *(float2*)&g_s2[(size_t)m0 * COUT + col] = make_float2(E[tile][0], E[tile][1]);
                *(float2*)&g_s2[(size_t)m1 * COUT + col] = make_float2(E[tile][2], E[tile][3]);
            }
        }
    }
}

// ---------------- launch --------------------------------------------------------
extern "C" void kernel_launch(void* const* d_in, const int* in_sizes, int n_in,
                              void* d_out, int out_size) {
    const float* nf   = (const float*)d_in[0];
    const int*   src1 = (const int*)  d_in[1];
    const int*   dst1 = (const int*)  d_in[2];
    const float* ew1  = (const float*)d_in[3];
    const int*   src2 = (const int*)  d_in[4];
    const int*   dst2 = (const int*)  d_in[5];
    const float* ew2  = (const float*)d_in[6];
    const float* W1s  = (const float*)d_in[7];
    const float* W1n  = (const float*)d_in[8];
    const float* b1   = (const float*)d_in[9];
    const float* W2s  = (const float*)d_in[10];
    const float* W2n  = (const float*)d_in[11];
    const float* b2   = (const float*)d_in[12];
    float* out = (float*)d_out;

    int nsrc = in_sizes[0] / (TT * CIN);   // 50000

    k_zero    <<<(N1C + 255) / 256, 256>>>();
    k_build   <<<(E1C + E2C + 255) / 256, 256>>>(src1, dst1, ew1, src2, dst2, ew2);
    k_agg1    <<<(N1C + 7) / 8, 256>>>(nf, nsrc);
    k_gemm_mma<<<ROWS1 / 128, 128>>>(nf, W1s, W1n, b1, W2s, W2n, nsrc);
    k_agg2f   <<<(N2C + 7) / 8, 256>>>(b2, out);
}

// round 17
// speedup vs baseline: 1.0721x; 1.0468x over previous
#include <cuda_runtime.h>
#include <cuda_bf16.h>
#include <cstdint>

// ---------------- fixed problem shapes ---------------------------------------
#define TT    12
#define CIN   32
#define HID   64
#define COUT  32
#define N1C   20000
#define N2C   10000
#define E1C   320000
#define E2C   160000
#define TC    (TT*CIN)        // 384
#define ROWS1 (N1C*TT)        // 240000 (= 1875 * 128)
#define ROWS2 (N2C*TT)        // 120000
#define CAP   96

// ---------------- device scratch (static, no runtime allocation) -------------
__device__ float g_agg1[(size_t)ROWS1 * CIN];
__device__ float g_z1  [(size_t)ROWS1 * COUT];
__device__ float g_s2  [(size_t)ROWS2 * COUT];
__device__ int   g_cnt1[N1C];
__device__ int   g_cnt2[N2C];
__device__ int2  g_buk1[(size_t)N1C * CAP];
__device__ int2  g_buk2[(size_t)N2C * CAP];

__device__ __forceinline__ float lrelu(float x) { return x > 0.f ? x : 0.01f * x; }

__device__ __forceinline__ void fma4(float4& a, float w, float4 v) {
    a.x += w * v.x; a.y += w * v.y; a.z += w * v.z; a.w += w * v.w;
}
__device__ __forceinline__ float4 add4(float4 a, float4 b) {
    return make_float4(a.x + b.x, a.y + b.y, a.z + b.z, a.w + b.w);
}

// split a float pair into hi/lo bf16x2 words (x -> low 16 bits)
__device__ __forceinline__ void cvthl(float x, float y, uint32_t& h, uint32_t& l) {
    __nv_bfloat16 hx = __float2bfloat16(x), hy = __float2bfloat16(y);
    __nv_bfloat16 lx = __float2bfloat16(x - __bfloat162float(hx));
    __nv_bfloat16 ly = __float2bfloat16(y - __bfloat162float(hy));
    __nv_bfloat162 hp(hx, hy), lp(lx, ly);
    h = *reinterpret_cast<uint32_t*>(&hp);
    l = *reinterpret_cast<uint32_t*>(&lp);
}

// HMMA m16n8k16 row.col bf16 -> f32
__device__ __forceinline__ void mma16816(float* d, const uint32_t* a, uint32_t b0, uint32_t b1) {
    asm volatile(
        "mma.sync.aligned.m16n8k16.row.col.f32.bf16.bf16.f32 "
        "{%0,%1,%2,%3}, {%4,%5,%6,%7}, {%8,%9}, {%0,%1,%2,%3};"
        : "+f"(d[0]), "+f"(d[1]), "+f"(d[2]), "+f"(d[3])
        : "r"(a[0]), "r"(a[1]), "r"(a[2]), "r"(a[3]), "r"(b0), "r"(b1));
}

// ---------------- bucket build (R12 verbatim) ----------------------------------
__global__ void k_zero() {
    int i = blockIdx.x * blockDim.x + threadIdx.x;
    if (i < N1C) g_cnt1[i] = 0;
    if (i < N2C) g_cnt2[i] = 0;
}

__global__ void k_build(const int* __restrict__ src1, const int* __restrict__ dst1,
                        const float* __restrict__ ew1,
                        const int* __restrict__ src2, const int* __restrict__ dst2,
                        const float* __restrict__ ew2) {
    int i = blockIdx.x * blockDim.x + threadIdx.x;
    if (i < E1C) {
        int d = dst1[i];
        int p = atomicAdd(&g_cnt1[d], 1);
        if (p < CAP) g_buk1[(size_t)d * CAP + p] = make_int2(src1[i], __float_as_int(ew1[i]));
    } else if (i < E1C + E2C) {
        int e = i - E1C;
        int d = dst2[e];
        int p = atomicAdd(&g_cnt2[d], 1);
        if (p < CAP) g_buk2[(size_t)d * CAP + p] = make_int2(src2[e], __float_as_int(ew2[e]));
    }
}

// ---------------- layer-1 aggregation (R12 verbatim: warp per dst) -------------
__global__ void __launch_bounds__(256) k_agg1(const float* __restrict__ nf, int nsrc) {
    int d = blockIdx.x * 8 + (threadIdx.x >> 5);
    if (d >= N1C) return;
    int lane = threadIdx.x & 31;
    int n = min(g_cnt1[d], CAP);
    const int2* eb = &g_buk1[(size_t)d * CAP];
    size_t plane = (size_t)nsrc * CIN;
    size_t o0 = (size_t)(lane >> 3) * plane + (lane & 7) * 4;
    size_t o1 = o0 + 4 * plane;
    size_t o2 = o1 + 4 * plane;
    float4 A0[3] = {}, A1[3] = {}, A2[3] = {}, A3[3] = {};
    int i = 0;
    for (; i + 4 <= n; i += 4) {
        int2 e0 = __ldg(&eb[i]),     e1 = __ldg(&eb[i + 1]);
        int2 e2 = __ldg(&eb[i + 2]), e3 = __ldg(&eb[i + 3]);
        const float* p0 = nf + (size_t)e0.x * CIN;
        const float* p1 = nf + (size_t)e1.x * CIN;
        const float* p2 = nf + (size_t)e2.x * CIN;
        const float* p3 = nf + (size_t)e3.x * CIN;
        float w0 = __int_as_float(e0.y), w1 = __int_as_float(e1.y);
        float w2 = __int_as_float(e2.y), w3 = __int_as_float(e3.y);
        fma4(A0[0], w0, __ldg((const float4*)(p0 + o0)));
        fma4(A1[0], w1, __ldg((const float4*)(p1 + o0)));
        fma4(A2[0], w2, __ldg((const float4*)(p2 + o0)));
        fma4(A3[0], w3, __ldg((const float4*)(p3 + o0)));
        fma4(A0[1], w0, __ldg((const float4*)(p0 + o1)));
        fma4(A1[1], w1, __ldg((const float4*)(p1 + o1)));
        fma4(A2[1], w2, __ldg((const float4*)(p2 + o1)));
        fma4(A3[1], w3, __ldg((const float4*)(p3 + o1)));
        fma4(A0[2], w0, __ldg((const float4*)(p0 + o2)));
        fma4(A1[2], w1, __ldg((const float4*)(p1 + o2)));
        fma4(A2[2], w2, __ldg((const float4*)(p2 + o2)));
        fma4(A3[2], w3, __ldg((const float4*)(p3 + o2)));
    }
    for (; i < n; i++) {
        int2 e = __ldg(&eb[i]);
        const float* p = nf + (size_t)e.x * CIN;
        float w = __int_as_float(e.y);
        fma4(A0[0], w, __ldg((const float4*)(p + o0)));
        fma4(A0[1], w, __ldg((const float4*)(p + o1)));
        fma4(A0[2], w, __ldg((const float4*)(p + o2)));
    }
    float* op = &g_agg1[(size_t)d * TC];
    *(float4*)(op + lane * 4)       = add4(add4(A0[0], A1[0]), add4(A2[0], A3[0]));
    *(float4*)(op + lane * 4 + 128) = add4(add4(A0[1], A1[1]), add4(A2[1], A3[1]));
    *(float4*)(op + lane * 4 + 256) = add4(add4(A0[2], A1[2]), add4(A2[2], A3[2]));
}

// ---------------- layer-2 aggregation + epilogue: 2 warps per dst --------------
// Warps (pair, half): half 0 takes edges [0, n/2), half 1 takes [n/2, n).
// Inner loop identical to R12's proven pipeline; partials combined via smem.
// 4 dsts per 256-thread block; N2C % 4 == 0 so no thread exits early.
__global__ void __launch_bounds__(256) k_agg2f(const float* __restrict__ b2,
                                               float* __restrict__ out) {
    __shared__ float sacc[4][TC];
    int wid = threadIdx.x >> 5;
    int pair = wid >> 1, half = wid & 1;
    int d = blockIdx.x * 4 + pair;
    int lane = threadIdx.x & 31;
    int n = min(g_cnt2[d], CAP);
    int beg = half ? (n >> 1) : 0;
    int end = half ? n : (n >> 1);
    const int2* eb = &g_buk2[(size_t)d * CAP];
    int u0 = lane * 4, u1 = u0 + 128, u2 = u1 + 128;
    float4 A0[3] = {}, A1[3] = {}, A2[3] = {}, A3[3] = {};
    int i = beg;
    for (; i + 4 <= end; i += 4) {
        int2 e0 = __ldg(&eb[i]),     e1 = __ldg(&eb[i + 1]);
        int2 e2 = __ldg(&eb[i + 2]), e3 = __ldg(&eb[i + 3]);
        const float* p0 = g_z1 + (size_t)e0.x * TC;
        const float* p1 = g_z1 + (size_t)e1.x * TC;
        const float* p2 = g_z1 + (size_t)e2.x * TC;
        const float* p3 = g_z1 + (size_t)e3.x * TC;
        float w0 = __int_as_float(e0.y), w1 = __int_as_float(e1.y);
        float w2 = __int_as_float(e2.y), w3 = __int_as_float(e3.y);
        fma4(A0[0], w0, __ldg((const float4*)(p0 + u0)));
        fma4(A1[0], w1, __ldg((const float4*)(p1 + u0)));
        fma4(A2[0], w2, __ldg((const float4*)(p2 + u0)));
        fma4(A3[0], w3, __ldg((const float4*)(p3 + u0)));
        fma4(A0[1], w0, __ldg((const float4*)(p0 + u1)));
        fma4(A1[1], w1, __ldg((const float4*)(p1 + u1)));
        fma4(A2[1], w2, __ldg((const float4*)(p2 + u1)));
        fma4(A3[1], w3, __ldg((const float4*)(p3 + u1)));
        fma4(A0[2], w0, __ldg((const float4*)(p0 + u2)));
        fma4(A1[2], w1, __ldg((const float4*)(p1 + u2)));
        fma4(A2[2], w2, __ldg((const float4*)(p2 + u2)));
        fma4(A3[2], w3, __ldg((const float4*)(p3 + u2)));
    }
    for (; i < end; i++) {
        int2 e = __ldg(&eb[i]);
        const float* p = g_z1 + (size_t)e.x * TC;
        float w = __int_as_float(e.y);
        fma4(A0[0], w, __ldg((const float4*)(p + u0)));
        fma4(A0[1], w, __ldg((const float4*)(p + u1)));
        fma4(A0[2], w, __ldg((const float4*)(p + u2)));
    }
    float4 R[3];
    R[0] = add4(add4(A0[0], A1[0]), add4(A2[0], A3[0]));
    R[1] = add4(add4(A0[1], A1[1]), add4(A2[1], A3[1]));
    R[2] = add4(add4(A0[2], A1[2]), add4(A2[2], A3[2]));
    if (half == 0) {
        #pragma unroll
        for (int j = 0; j < 3; j++)
            *(float4*)&sacc[pair][(lane + j * 32) * 4] = R[j];
    }
    __syncthreads();
    if (half == 1) {
        float4 bq = __ldg((const float4*)&b2[(lane & 7) * 4]);
        const float* sp = &g_s2[(size_t)d * TC];
        #pragma unroll
        for (int j = 0; j < 3; j++) {
            int q = lane + j * 32;
            float4 o = *(const float4*)&sacc[pair][q * 4];
            float4 s = *(const float4*)(sp + q * 4);
            float4 v;
            v.x = lrelu(R[j].x + o.x + s.x + bq.x);
            v.y = lrelu(R[j].y + o.y + s.y + bq.y);
            v.z = lrelu(R[j].z + o.z + s.z + bq.z);
            v.w = lrelu(R[j].w + o.w + s.w + bq.w);
            int t = q >> 3, cq = q & 7;
            *(float4*)&out[((size_t)t * N2C + d) * COUT + cq * 4] = v;
        }
    }
}

// ---------------- fused GEMM via mma.sync (R12 verbatim) -----------------------
__global__ void __launch_bounds__(256) k_gemm_mma(
        const float* __restrict__ nf,
        const float* __restrict__ W1s, const float* __restrict__ W1n,
        const float* __restrict__ b1,
        const float* __restrict__ W2s, const float* __restrict__ W2n,
        int nsrc) {
    __shared__ uint4 sW1[1024];   // 16 KB: stage-1 weights, fragment-packed
    __shared__ uint4 sW2[1024];   // 16 KB: stage-2 weights
    int tid = threadIdx.x;

    // prologue: pack W1' = [W1s|W1n] (n=h, k=cat) and W2' = [W2n;W2s] (k=h)
    for (int i = tid; i < 2048; i += 256) {
        int e = i & 1023;
        int ln = e & 31, s = (e >> 5) & 3, j = e >> 7;
        int n = j * 8 + (ln >> 2);
        int k = s * 16 + (ln & 3) * 2;
        const float* base;
        if (i < 1024) base = (s < 2) ? &W1s[n * 32 + k] : &W1n[n * 32 + (k - 32)];
        else          base = (n < 32) ? &W2n[n * 64 + k] : &W2s[(n - 32) * 64 + k];
        uint32_t b0h, b0l, b1h, b1l;
        cvthl(__ldg(base),     __ldg(base + 1), b0h, b0l);
        cvthl(__ldg(base + 8), __ldg(base + 9), b1h, b1l);
        (i < 1024 ? sW1 : sW2)[e] = make_uint4(b0h, b0l, b1h, b1l);
    }
    __syncthreads();

    int lane = tid & 31, wid = tid >> 5;
    int mb = blockIdx.x * 128 + wid * 16;
    int m0 = mb + (lane >> 2), m1 = m0 + 8;
    int ko = (lane & 3) * 2;

    // stage-1 A fragments straight from gmem (hi/lo split)
    uint32_t Ah[4][4], Al[4][4];
    {
        int nd0 = m0 / TT, t0 = m0 - nd0 * TT;
        int nd1 = m1 / TT, t1 = m1 - nd1 * TT;
        const float* p0 = &nf[((size_t)t0 * nsrc + nd0) * CIN];
        const float* p1 = &nf[((size_t)t1 * nsrc + nd1) * CIN];
        const float* q0 = &g_agg1[(size_t)m0 * CIN];
        const float* q1 = &g_agg1[(size_t)m1 * CIN];
        #pragma unroll
        for (int s = 0; s < 4; s++) {
            int k = s * 16 + ko;
            const float* r0p = (s < 2) ? p0 + k : q0 + (k - 32);
            const float* r1p = (s < 2) ? p1 + k : q1 + (k - 32);
            float2 v0 = *(const float2*)r0p;
            float2 v1 = *(const float2*)r1p;
            float2 v2 = *(const float2*)(r0p + 8);
            float2 v3 = *(const float2*)(r1p + 8);
            cvthl(v0.x, v0.y, Ah[s][0], Al[s][0]);
            cvthl(v1.x, v1.y, Ah[s][1], Al[s][1]);
            cvthl(v2.x, v2.y, Ah[s][2], Al[s][2]);
            cvthl(v3.x, v3.y, Ah[s][3], Al[s][3]);
        }
    }

    // stage 1: D = A @ W1'^T (3 split terms), K=64
    float D[8][4];
    #pragma unroll
    for (int j = 0; j < 8; j++) D[j][0] = D[j][1] = D[j][2] = D[j][3] = 0.f;
    #pragma unroll
    for (int j = 0; j < 8; j++)
        #pragma unroll
        for (int s = 0; s < 4; s++) {
            uint4 w = sW1[(j * 4 + s) * 32 + lane];
            mma16816(D[j], Ah[s], w.x, w.z);
            mma16816(D[j], Al[s], w.x, w.z);
            mma16816(D[j], Ah[s], w.y, w.w);
        }

    // bias + leaky relu (h1, in registers)
    #pragma unroll
    for (int j = 0; j < 8; j++) {
        int n0 = j * 8 + ko;
        float be = __ldg(&b1[n0]), bo = __ldg(&b1[n0 + 1]);
        D[j][0] = lrelu(D[j][0] + be); D[j][1] = lrelu(D[j][1] + bo);
        D[j][2] = lrelu(D[j][2] + be); D[j][3] = lrelu(D[j][3] + bo);
    }

    // stage-2 A fragments: direct register relayout of D
    uint32_t Bh[4][4], Bl[4][4];
    #pragma unroll
    for (int s = 0; s < 4; s++) {
        cvthl(D[2*s][0],   D[2*s][1],   Bh[s][0], Bl[s][0]);
        cvthl(D[2*s][2],   D[2*s][3],   Bh[s][1], Bl[s][1]);
        cvthl(D[2*s+1][0], D[2*s+1][1], Bh[s][2], Bl[s][2]);
        cvthl(D[2*s+1][2], D[2*s+1][3], Bh[s][3], Bl[s][3]);
    }

    // stage 2: [z1 | s2] = h1 @ W2'^T; skip s-half when warp rows >= ROWS2
    int jmax = (mb < ROWS2) ? 8 : 4;
    for (int j2 = 0; j2 < jmax; j2++) {
        float E[4] = {0.f, 0.f, 0.f, 0.f};
        #pragma unroll
        for (int s = 0; s < 4; s++) {
            uint4 w = sW2[(j2 * 4 + s) * 32 + lane];
            mma16816(E, Bh[s], w.x, w.z);
            mma16816(E, Bl[s], w.x, w.z);
            mma16816(E, Bh[s], w.y, w.w);
        }
        if (j2 < 4) {
            int col = j2 * 8 + ko;
            *(float2*)&g_z1[(size_t)m0 * COUT + col] = make_float2(E[0], E[1]);
            *(float2*)&g_z1[(size_t)m1 * COUT + col] = make_float2(E[2], E[3]);
        } else {
            int col = (j2 - 4) * 8 + ko;
            if (m0 < ROWS2) *(float2*)&g_s2[(size_t)m0 * COUT + col] = make_float2(E[0], E[1]);
            if (m1 < ROWS2) *(float2*)&g_s2[(size_t)m1 * COUT + col] = make_float2(E[2], E[3]);
        }
    }
}

// ---------------- launch --------------------------------------------------------
extern "C" void kernel_launch(void* const* d_in, const int* in_sizes, int n_in,
                              void* d_out, int out_size) {
    const float* nf   = (const float*)d_in[0];
    const int*   src1 = (const int*)  d_in[1];
    const int*   dst1 = (const int*)  d_in[2];
    const float* ew1  = (const float*)d_in[3];
    const int*   src2 = (const int*)  d_in[4];
    const int*   dst2 = (const int*)  d_in[5];
    const float* ew2  = (const float*)d_in[6];
    const float* W1s  = (const float*)d_in[7];
    const float* W1n  = (const float*)d_in[8];
    const float* b1   = (const float*)d_in[9];
    const float* W2s  = (const float*)d_in[10];
    const float* W2n  = (const float*)d_in[11];
    const float* b2   = (const float*)d_in[12];
    float* out = (float*)d_out;

    int nsrc = in_sizes[0] / (TT * CIN);   // 50000

    k_zero    <<<(N1C + 255) / 256, 256>>>();
    k_build   <<<(E1C + E2C + 255) / 256, 256>>>(src1, dst1, ew1, src2, dst2, ew2);
    k_agg1    <<<(N1C + 7) / 8, 256>>>(nf, nsrc);
    k_gemm_mma<<<ROWS1 / 128, 256>>>(nf, W1s, W1n, b1, W2s, W2n, nsrc);
    k_agg2f   <<<N2C / 4, 256>>>(b2, out);
}